// round 5
// baseline (speedup 1.0000x reference)
#include <cuda_runtime.h>
#include <cstdint>

// ---------------------------------------------------------------------------
// Compile-time LUT construction (replicates the numpy table builders exactly)
// NOTE: all locals value-initialized — nvcc's constexpr evaluator (C++17
// rules) rejects uninitialized variables in constexpr functions.
// ---------------------------------------------------------------------------
struct LUTs {
    int tbl64[64];   // packed: ptype | rot<<2 | flip<<4, keyed by 6 pairwise <= bits
    int wA[17], wB[17], wC[17];  // lex-rank prefix tables for sorted tuples
};

static constexpr LUTs make_luts() {
    LUTs L = {};
    // ---- symmetry maps over rank permutations (256-entry, base-4 packed) ----
    int tm[256] = {}, rm[256] = {}, fm[256] = {};
    for (int i = 0; i < 256; i++) { tm[i] = 10; rm[i] = 10; fm[i] = 10; }
    const int pats[3][4] = { {0,1,2,3}, {0,1,3,2}, {0,2,3,1} };
    for (int pt = 0; pt < 3; ++pt) {
        int p[4] = { pats[pt][0], pats[pt][1], pats[pt][2], pats[pt][3] };
        for (int fl = 0; fl < 2; ++fl) {
            for (int ro = 0; ro < 4; ++ro) {
                int q[4] = { p[0], p[1], p[2], p[3] };
                // np.rot90 applied 'ro' times: [[e0,e1],[e2,e3]] -> [[e1,e3],[e0,e2]]
                for (int k = 0; k < ro; k++) {
                    int t0 = q[0], t1 = q[1], t2 = q[2], t3 = q[3];
                    q[0] = t1; q[1] = t3; q[2] = t0; q[3] = t2;
                }
                int id = ((q[0]*4 + q[1])*4 + q[2])*4 + q[3];
                tm[id] = pt; rm[id] = ro; fm[id] = fl;
            }
            // p = p[:, ::-1]
            int t0 = p[0], t1 = p[1], t2 = p[2], t3 = p[3];
            p[0] = t1; p[1] = t0; p[2] = t3; p[3] = t2;
        }
    }
    // ---- 64-entry table keyed by stable-comparison bits ----
    for (int key = 0; key < 64; ++key) {
        int p01 =  key       & 1;
        int p02 = (key >> 1) & 1;
        int p03 = (key >> 2) & 1;
        int p12 = (key >> 3) & 1;
        int p13 = (key >> 4) & 1;
        int p23 = (key >> 5) & 1;
        // stable ranks: for pair (j<k), p_jk = (v_j <= v_k); ties -> earlier pos wins
        int r0 = (1-p01) + (1-p02) + (1-p03);
        int r1 = p01 + (1-p12) + (1-p13);
        int r2 = p02 + p12 + (1-p23);
        int r3 = p03 + p13 + p23;
        int rr[4] = { r0, r1, r2, r3 };
        int seen[4] = {0,0,0,0};
        bool ok = true;
        for (int k = 0; k < 4; k++) {
            if (rr[k] < 0 || rr[k] > 3) { ok = false; break; }
            seen[rr[k]]++;
        }
        if (ok) for (int k = 0; k < 4; k++) if (seen[k] != 1) ok = false;
        int val = 0;
        if (ok) {
            int id = ((r0*4 + r1)*4 + r2)*4 + r3;
            int ty = tm[id], ro = rm[id], fl = fm[id];
            if (ty > 2) ty = 2;           // unreachable (orbits cover S4), faithful fallback
            if (ro > 3) ro = 0;
            if (fl > 1) fl = 0;
            val = ty | (ro << 2) | (fl << 4);
        }
        L.tbl64[key] = val;
    }
    // ---- widx = lex rank of nondecreasing (s0<=s1<=s2<=s3) over 0..16 ----
    // rank = S3[s0] + (S2[s1]-S2[s0]) + (S1[s2]-S1[s1]) + (s3 - s2)
    //      = A[s0] + B[s1] + C[s2] + s3
    int S1 = 0, S2 = 0, S3 = 0;
    for (int x = 0; x < 17; ++x) {
        L.wA[x] = S3 - S2;
        L.wB[x] = S2 - S1;
        L.wC[x] = S1 - x;
        S1 += 17 - x;                                  // M1(x) = 17-x
        S2 += (18 - x) * (17 - x) / 2;                 // M2(x) = C(18-x,2)
        S3 += (19 - x) * (18 - x) * (17 - x) / 6;      // M3(x) = C(19-x,3)
    }
    return L;
}

__constant__ LUTs g_luts = make_luts();

// ---------------------------------------------------------------------------
// Kernel: 4 lanes cooperate on one index. Lane r owns output row r.
// ---------------------------------------------------------------------------
__global__ __launch_bounds__(256)
void lut_symmetric_kernel(const int*   __restrict__ index,
                          const float* __restrict__ w0,
                          const float* __restrict__ w1,
                          const float* __restrict__ w2,
                          float*       __restrict__ out,
                          int n)
{
    __shared__ int s_tbl[64];
    __shared__ int sA[17], sB[17], sC[17];
    {
        int tid = threadIdx.x;
        if (tid < 64)                 s_tbl[tid]    = g_luts.tbl64[tid];
        if (tid >= 64  && tid < 81)   sA[tid - 64]  = g_luts.wA[tid - 64];
        if (tid >= 96  && tid < 113)  sB[tid - 96]  = g_luts.wB[tid - 96];
        if (tid >= 128 && tid < 145)  sC[tid - 128] = g_luts.wC[tid - 128];
    }
    __syncthreads();

    unsigned gid = blockIdx.x * blockDim.x + threadIdx.x;
    unsigned idx = gid >> 2;          // index id
    int r = gid & 3;                  // output row owned by this lane
    bool valid = idx < (unsigned)n;
    if (!valid) idx = 0;              // keep all lanes alive for shuffles

    // ---- decode base-17 digits ----
    unsigned i = (unsigned)__ldg(&index[idx]);
    unsigned d = i % 17u; i /= 17u;
    unsigned c = i % 17u; i /= 17u;
    unsigned b = i % 17u;
    unsigned a = i / 17u;

    // ---- symmetry class from pairwise comparison bits ----
    int key =  (int)(a <= b)
            | ((int)(a <= c) << 1)
            | ((int)(a <= d) << 2)
            | ((int)(b <= c) << 3)
            | ((int)(b <= d) << 4)
            | ((int)(c <= d) << 5);
    int packed = s_tbl[key];
    int ty = packed & 3;
    int ro = (packed >> 2) & 3;
    int fl = (packed >> 4) & 1;

    // ---- sort digits (network) -> lex rank -> widx ----
    unsigned l0 = min(a, b), h0 = max(a, b);
    unsigned l1 = min(c, d), h1 = max(c, d);
    unsigned s0 = min(l0, l1), m0 = max(l0, l1);
    unsigned m1 = min(h0, h1), s3 = max(h0, h1);
    unsigned s1 = min(m0, m1), s2 = max(m0, m1);
    int widx = sA[s0] + sB[s1] + sC[s2] + (int)s3;

    // ---- gather this lane's source row (64B-granule cooperative) ----
    const float* wp = (ty == 0) ? w0 : ((ty == 1) ? w1 : w2);
    float4 av = *reinterpret_cast<const float4*>(wp + (unsigned)widx * 16u + (unsigned)r * 4u);

    // ---- round (half-to-even, == jnp.round) + clip, commutes with permutation ----
    float a0 = fminf(fmaxf(rintf(av.x), -128.0f), 127.0f);
    float a1 = fminf(fmaxf(rintf(av.y), -128.0f), 127.0f);
    float a2 = fminf(fmaxf(rintf(av.z), -128.0f), 127.0f);
    float a3 = fminf(fmaxf(rintf(av.w), -128.0f), 127.0f);

    const unsigned FULL = 0xffffffffu;

    // ---- butterfly transpose of the 4x4 tile across the 4-lane group ----
    // After: t_r[k] = B[k][r]  (column r, indexed by row k)
    float x1 = __shfl_xor_sync(FULL, a1, 1);
    float x0 = __shfl_xor_sync(FULL, a0, 1);
    float x3 = __shfl_xor_sync(FULL, a3, 1);
    float x2 = __shfl_xor_sync(FULL, a2, 1);
    bool rb0 = (r & 1) != 0;
    float b0 = rb0 ? x1 : a0;
    float b1 = rb0 ? a1 : x0;
    float b2 = rb0 ? x3 : a2;
    float b3 = rb0 ? a3 : x2;

    float y2 = __shfl_xor_sync(FULL, b2, 2);
    float y3 = __shfl_xor_sync(FULL, b3, 2);
    float y0 = __shfl_xor_sync(FULL, b0, 2);
    float y1 = __shfl_xor_sync(FULL, b1, 2);
    bool rb1 = (r & 2) != 0;
    float t0 = rb1 ? y2 : b0;
    float t1 = rb1 ? y3 : b1;
    float t2 = rb1 ? b2 : y0;
    float t3 = rb1 ? b3 : y1;

    // ---- per-row source selection ----
    // out[r][j]: rot0: B[r][fl?3-j:j]      rot1: B[j][fl?r:3-r]
    //            rot2: B[3-r][fl?j:3-j]    rot3: B[3-j][fl?3-r:r]
    int  rr3  = 3 - r;
    bool odd  = (ro & 1) != 0;
    int  lEven = (ro == 0) ? r : rr3;
    int  lOdd  = ((fl ^ (int)(ro == 3)) != 0) ? r : rr3;
    int  srcl  = odd ? lOdd : lEven;
    bool rev   = odd ? (ro == 3) : ((fl ^ (int)(ro == 2)) != 0);

    float v0 = odd ? t0 : a0;
    float v1 = odd ? t1 : a1;
    float v2 = odd ? t2 : a2;
    float v3 = odd ? t3 : a3;

    float g0 = __shfl_sync(FULL, v0, srcl, 4);
    float g1 = __shfl_sync(FULL, v1, srcl, 4);
    float g2 = __shfl_sync(FULL, v2, srcl, 4);
    float g3 = __shfl_sync(FULL, v3, srcl, 4);

    float o0 = rev ? g3 : g0;
    float o1 = rev ? g2 : g1;
    float o2 = rev ? g1 : g2;
    float o3 = rev ? g0 : g3;

    if (valid) {
        *reinterpret_cast<float4*>(out + (size_t)idx * 16u + (unsigned)r * 4u)
            = make_float4(o0, o1, o2, o3);
    }
}

// ---------------------------------------------------------------------------
// Harness entry
// ---------------------------------------------------------------------------
extern "C" void kernel_launch(void* const* d_in, const int* in_sizes, int n_in,
                              void* d_out, int out_size)
{
    const int*   index = (const int*)  d_in[0];
    const float* w0    = (const float*)d_in[1];
    const float* w1    = (const float*)d_in[2];
    const float* w2    = (const float*)d_in[3];
    float*       out   = (float*)      d_out;
    int n = in_sizes[0];

    unsigned total = (unsigned)n * 4u;
    unsigned block = 256;
    unsigned grid  = (total + block - 1) / block;
    lut_symmetric_kernel<<<grid, block>>>(index, w0, w1, w2, out, n);
}